// round 15
// baseline (speedup 1.0000x reference)
#include <cuda_runtime.h>
#include <cuda_bf16.h>

// Problem constants (fixed by setup_inputs)
#define RR   8
#define BB   8
#define LL   2048
#define PP   16384
#define HQ   32
#define HKV  8
#define GG   4
#define DK   128
#define DV   128
#define NWARPS 8
#define CC   4                  // token chunks per (r,b,h) for load balance
#define CHUNK (LL / CC)         // 512 tokens per chunk (even)
#define RC   (RR * CC)          // 32 partials per (b,h)
#define KVSTRIDE (HKV * DK)     // floats per page row
#define SCALE 0.08838834764831845f
#define NEGV  -1e30f
#define FULL 0xffffffffu

// Scratch (allocation-free rule: __device__ globals)
__device__ float g_O[RC * BB * HKV * GG * DV];    // normalized partial outputs (4 MB)
__device__ float g_lse[RC * BB * HQ];             // per-partial lse

__global__ __launch_bounds__(256, 2) void spgqa_decode_kernel(
    const float* __restrict__ q,
    const float* __restrict__ k_cache,
    const float* __restrict__ v_cache,
    const int*   __restrict__ kv_lens,
    const int*   __restrict__ btab)
{
    const int h    = blockIdx.x;          // kv head
    const int b    = blockIdx.y;          // batch
    const int rc   = blockIdx.z;          // split*CC + chunk
    const int r    = rc >> 2;
    const int c    = rc & 3;
    const int tid  = threadIdx.x;
    const int warp = tid >> 5;
    const int lane = tid & 31;

    int len = kv_lens[r * BB + b];
    if (len > LL) len = LL;
    if (len < 0)  len = 0;
    const int lo = c * CHUNK;             // even
    const int hi = min(len, lo + CHUNK);

    // Q fragment: lane holds dims [4*lane, 4*lane+4) for each of G query heads,
    // pre-scaled so the dot is already the score.
    float4 qf[GG];
#pragma unroll
    for (int g = 0; g < GG; g++) {
        float4 t = *(const float4*)&q[((size_t)b * HQ + (size_t)h * GG + g) * DK + lane * 4];
        t.x *= SCALE; t.y *= SCALE; t.z *= SCALE; t.w *= SCALE;
        qf[g] = t;
    }

    const int*   bt    = btab + ((size_t)r * BB + b) * LL;
    const float* kbase = k_cache + ((size_t)r * PP) * KVSTRIDE + (size_t)h * DK + lane * 4;
    const float* vbase = v_cache + ((size_t)r * PP) * KVSTRIDE + (size_t)h * DK + lane * 4;

    // Per-lane softmax state: head g = lane&3, token-parity tpar = (lane>>2)&1.
    // m replicated across all 8 lanes of a head; s accumulates only own-parity p.
    float m = NEGV, s = 0.f;
    float4 acc[GG];
#pragma unroll
    for (int g = 0; g < GG; g++) acc[g] = make_float4(0.f, 0.f, 0.f, 0.f);

    const bool fold0 = (lane & 1);
    const bool fold1 = (lane & 2);
    const bool fold2 = (lane & 4);
    const float4 z4 = make_float4(0.f, 0.f, 0.f, 0.f);

    // ---- depth-2 pipeline over token PAIRS: 4 LDG.128 in flight per slot ----
    float4 ka[2], kb[2], va[2], vb[2];
#pragma unroll
    for (int i = 0; i < 2; i++) {
        ka[i] = kb[i] = va[i] = vb[i] = z4;
        const int t0 = lo + 2 * (warp + i * NWARPS);
        if (t0 < hi) {
            const int2 pg = __ldg((const int2*)(bt + t0));   // t0 even, 8B-aligned
            ka[i] = __ldcs((const float4*)(kbase + (size_t)pg.x * KVSTRIDE));
            va[i] = __ldcs((const float4*)(vbase + (size_t)pg.x * KVSTRIDE));
            if (t0 + 1 < hi) {
                kb[i] = __ldcs((const float4*)(kbase + (size_t)pg.y * KVSTRIDE));
                vb[i] = __ldcs((const float4*)(vbase + (size_t)pg.y * KVSTRIDE));
            }
        }
    }
    int2 nextpg = make_int2(0, 0);
    {
        const int tp = lo + 2 * (warp + 2 * NWARPS);
        if (tp < hi) nextpg = __ldg((const int2*)(bt + tp));
    }

    int slot = 0;
    for (int t0 = lo + 2 * warp; t0 < hi; t0 += 2 * NWARPS, slot ^= 1) {
        const float4 k4a = ka[slot], k4b = kb[slot];
        const float4 v4a = va[slot], v4b = vb[slot];
        const bool   p1v = (t0 + 1 < hi);

        // Prefetch the pair 2 iterations ahead into the freed slot.
        const int tp = t0 + 4 * NWARPS;
        if (tp < hi) {
            ka[slot] = __ldcs((const float4*)(kbase + (size_t)nextpg.x * KVSTRIDE));
            va[slot] = __ldcs((const float4*)(vbase + (size_t)nextpg.x * KVSTRIDE));
            if (tp + 1 < hi) {
                kb[slot] = __ldcs((const float4*)(kbase + (size_t)nextpg.y * KVSTRIDE));
                vb[slot] = __ldcs((const float4*)(vbase + (size_t)nextpg.y * KVSTRIDE));
            } else { kb[slot] = z4; vb[slot] = z4; }
            const int tq = tp + 2 * NWARPS;
            if (tq < hi) nextpg = __ldg((const int2*)(bt + tq));
        }

        // 8 partial dots: 4 heads x 2 tokens, this lane's 4 dims.
        float dA0 = qf[0].x*k4a.x + qf[0].y*k4a.y + qf[0].z*k4a.z + qf[0].w*k4a.w;
        float dA1 = qf[1].x*k4a.x + qf[1].y*k4a.y + qf[1].z*k4a.z + qf[1].w*k4a.w;
        float dA2 = qf[2].x*k4a.x + qf[2].y*k4a.y + qf[2].z*k4a.z + qf[2].w*k4a.w;
        float dA3 = qf[3].x*k4a.x + qf[3].y*k4a.y + qf[3].z*k4a.z + qf[3].w*k4a.w;
        float dB0 = qf[0].x*k4b.x + qf[0].y*k4b.y + qf[0].z*k4b.z + qf[0].w*k4b.w;
        float dB1 = qf[1].x*k4b.x + qf[1].y*k4b.y + qf[1].z*k4b.z + qf[1].w*k4b.w;
        float dB2 = qf[2].x*k4b.x + qf[2].y*k4b.y + qf[2].z*k4b.z + qf[2].w*k4b.w;
        float dB3 = qf[3].x*k4b.x + qf[3].y*k4b.y + qf[3].z*k4b.z + qf[3].w*k4b.w;

        // Fold-reduce: 9 shfls give lane (g=lane&3, tpar=(lane>>2)&1) the full
        // 32-lane dot for its (head, token).
        float eA0 = (fold0 ? dA1 : dA0) + __shfl_xor_sync(FULL, fold0 ? dA0 : dA1, 1);
        float eA1 = (fold0 ? dA3 : dA2) + __shfl_xor_sync(FULL, fold0 ? dA2 : dA3, 1);
        float eB0 = (fold0 ? dB1 : dB0) + __shfl_xor_sync(FULL, fold0 ? dB0 : dB1, 1);
        float eB1 = (fold0 ? dB3 : dB2) + __shfl_xor_sync(FULL, fold0 ? dB2 : dB3, 1);
        float fA  = (fold1 ? eA1 : eA0) + __shfl_xor_sync(FULL, fold1 ? eA0 : eA1, 2);
        float fB  = (fold1 ? eB1 : eB0) + __shfl_xor_sync(FULL, fold1 ? eB0 : eB1, 2);
        float sc  = (fold2 ? fB  : fA ) + __shfl_xor_sync(FULL, fold2 ? fA  : fB , 4);
        sc += __shfl_xor_sync(FULL, sc, 8);
        sc += __shfl_xor_sync(FULL, sc, 16);

        // Mask invalid odd-tail token (warp-uniform condition).
        if (fold2 && !p1v) sc = NEGV;

        // Partner token's score for this head (for the shared max).
        const float sco  = __shfl_xor_sync(FULL, sc, 4);
        const float smax = fmaxf(sc, sco);

        const unsigned upd = __ballot_sync(FULL, smax > m);
        if (upd == 0u) {
            // Fast path: running max unchanged.
            const float p = __expf(sc - m);
            s += p;
            const float p00 = __shfl_sync(FULL, p, 0);
            const float p01 = __shfl_sync(FULL, p, 1);
            const float p02 = __shfl_sync(FULL, p, 2);
            const float p03 = __shfl_sync(FULL, p, 3);
            const float p10 = __shfl_sync(FULL, p, 4);
            const float p11 = __shfl_sync(FULL, p, 5);
            const float p12 = __shfl_sync(FULL, p, 6);
            const float p13 = __shfl_sync(FULL, p, 7);
            acc[0].x += p00*v4a.x + p10*v4b.x;  acc[0].y += p00*v4a.y + p10*v4b.y;
            acc[0].z += p00*v4a.z + p10*v4b.z;  acc[0].w += p00*v4a.w + p10*v4b.w;
            acc[1].x += p01*v4a.x + p11*v4b.x;  acc[1].y += p01*v4a.y + p11*v4b.y;
            acc[1].z += p01*v4a.z + p11*v4b.z;  acc[1].w += p01*v4a.w + p11*v4b.w;
            acc[2].x += p02*v4a.x + p12*v4b.x;  acc[2].y += p02*v4a.y + p12*v4b.y;
            acc[2].z += p02*v4a.z + p12*v4b.z;  acc[2].w += p02*v4a.w + p12*v4b.w;
            acc[3].x += p03*v4a.x + p13*v4b.x;  acc[3].y += p03*v4a.y + p13*v4b.y;
            acc[3].z += p03*v4a.z + p13*v4b.z;  acc[3].w += p03*v4a.w + p13*v4b.w;
        } else {
            const float nm = fmaxf(m, smax);
            const float cf = __expf(m - nm);
            const float p  = __expf(sc - nm);
            s = s * cf + p;
            m = nm;
            const float c0  = __shfl_sync(FULL, cf, 0);
            const float c1  = __shfl_sync(FULL, cf, 1);
            const float c2  = __shfl_sync(FULL, cf, 2);
            const float c3  = __shfl_sync(FULL, cf, 3);
            const float p00 = __shfl_sync(FULL, p, 0);
            const float p01 = __shfl_sync(FULL, p, 1);
            const float p02 = __shfl_sync(FULL, p, 2);
            const float p03 = __shfl_sync(FULL, p, 3);
            const float p10 = __shfl_sync(FULL, p, 4);
            const float p11 = __shfl_sync(FULL, p, 5);
            const float p12 = __shfl_sync(FULL, p, 6);
            const float p13 = __shfl_sync(FULL, p, 7);
            acc[0].x = acc[0].x*c0 + p00*v4a.x + p10*v4b.x;
            acc[0].y = acc[0].y*c0 + p00*v4a.y + p10*v4b.y;
            acc[0].z = acc[0].z*c0 + p00*v4a.z + p10*v4b.z;
            acc[0].w = acc[0].w*c0 + p00*v4a.w + p10*v4b.w;
            acc[1].x = acc[1].x*c1 + p01*v4a.x + p11*v4b.x;
            acc[1].y = acc[1].y*c1 + p01*v4a.y + p11*v4b.y;
            acc[1].z = acc[1].z*c1 + p01*v4a.z + p11*v4b.z;
            acc[1].w = acc[1].w*c1 + p01*v4a.w + p11*v4b.w;
            acc[2].x = acc[2].x*c2 + p02*v4a.x + p12*v4b.x;
            acc[2].y = acc[2].y*c2 + p02*v4a.y + p12*v4b.y;
            acc[2].z = acc[2].z*c2 + p02*v4a.z + p12*v4b.z;
            acc[2].w = acc[2].w*c2 + p02*v4a.w + p12*v4b.w;
            acc[3].x = acc[3].x*c3 + p03*v4a.x + p13*v4b.x;
            acc[3].y = acc[3].y*c3 + p03*v4a.y + p13*v4b.y;
            acc[3].z = acc[3].z*c3 + p03*v4a.z + p13*v4b.z;
            acc[3].w = acc[3].w*c3 + p03*v4a.w + p13*v4b.w;
        }
    }

    // Merge the two token-parity streams of each head: s_tot replicated.
    const float s_tot = s + __shfl_xor_sync(FULL, s, 4);

    // Cross-warp merge in shared memory
    __shared__ float sm[NWARPS][GG];
    __shared__ float ss[NWARPS][GG];
    __shared__ float sacc[NWARPS][GG][DV];

#pragma unroll
    for (int g = 0; g < GG; g++) {
        sacc[warp][g][lane * 4 + 0] = acc[g].x;
        sacc[warp][g][lane * 4 + 1] = acc[g].y;
        sacc[warp][g][lane * 4 + 2] = acc[g].z;
        sacc[warp][g][lane * 4 + 3] = acc[g].w;
    }
    if (lane < GG) { sm[warp][lane] = m; ss[warp][lane] = s_tot; }  // lane&3==lane for lane<4
    __syncthreads();

    if (warp < GG) {
        const int g = warp;
        float M = NEGV;
#pragma unroll
        for (int w = 0; w < NWARPS; w++) M = fmaxf(M, sm[w][g]);

        float S = 0.f;
        float cw[NWARPS];
#pragma unroll
        for (int w = 0; w < NWARPS; w++) {
            cw[w] = __expf(sm[w][g] - M);
            S += ss[w][g] * cw[w];
        }

        float4 o = make_float4(0.f, 0.f, 0.f, 0.f);
#pragma unroll
        for (int w = 0; w < NWARPS; w++) {
            const float wc = cw[w];
            o.x += wc * sacc[w][g][lane * 4 + 0];
            o.y += wc * sacc[w][g][lane * 4 + 1];
            o.z += wc * sacc[w][g][lane * 4 + 2];
            o.w += wc * sacc[w][g][lane * 4 + 3];
        }

        const float Sc  = fmaxf(S, 1e-30f);
        const float inv = 1.0f / Sc;
        float* Od = &g_O[((((size_t)rc * BB + b) * HKV + h) * GG + g) * DV + lane * 4];
        Od[0] = o.x * inv; Od[1] = o.y * inv; Od[2] = o.z * inv; Od[3] = o.w * inv;

        if (lane == 0)
            g_lse[((size_t)rc * BB + b) * HQ + h * GG + g] = M + logf(Sc);
    }
}

// Flat combine over all RC=32 partials (softmax-merge associativity makes this
// equal to the reference's per-r-then-across-r two-stage combine, including
// the 1e-30 clamps and empty-split behavior).
__global__ __launch_bounds__(128) void spgqa_combine_kernel(float* __restrict__ out)
{
    const int bh = blockIdx.x;       // 0..B*HQ-1
    const int b  = bh / HQ;
    const int hq = bh % HQ;
    const int h  = hq / GG;
    const int g  = hq % GG;
    const int d  = threadIdx.x;      // 0..127

    __shared__ float slse[RC];
    if (threadIdx.x < RC)
        slse[threadIdx.x] = g_lse[((size_t)threadIdx.x * BB + b) * HQ + hq];
    __syncthreads();

    float gm = NEGV;
#pragma unroll
    for (int p = 0; p < RC; p++) gm = fmaxf(gm, slse[p]);

    float wsum = 0.f;
    float accv = 0.f;
#pragma unroll
    for (int p = 0; p < RC; p++) {
        const float w = __expf(slse[p] - gm);
        wsum += w;
        accv += w * g_O[((((size_t)p * BB + b) * HKV + h) * GG + g) * DV + d];
    }
    wsum = fmaxf(wsum, 1e-30f);

    out[((size_t)b * HQ + hq) * DV + d] = accv / wsum;
}

extern "C" void kernel_launch(void* const* d_in, const int* in_sizes, int n_in,
                              void* d_out, int out_size)
{
    const float* q        = (const float*)d_in[0];
    const float* k_cache  = (const float*)d_in[1];
    const float* v_cache  = (const float*)d_in[2];
    const int*   kv_lens  = (const int*)d_in[3];
    const int*   btab     = (const int*)d_in[4];
    float*       out      = (float*)d_out;

    dim3 grid1(HKV, BB, RC);
    spgqa_decode_kernel<<<grid1, 256>>>(q, k_cache, v_cache, kv_lens, btab);
    spgqa_combine_kernel<<<BB * HQ, 128>>>(out);
}